// round 1
// baseline (speedup 1.0000x reference)
#include <cuda_runtime.h>
#include <cstdint>
#include <cstddef>

// Problem constants
#define BATCH 4
#define NQ    2048
#define NK    2048
#define EMB   512
#define NH    8
#define HD    64
#define NTOK  (BATCH * NQ)          // 8192
#define SPM_N (BATCH * NQ * NK)     // 16777216

// ---------------- device-global scratch (no allocations allowed) -------------
__device__ float g_qn [NTOK * EMB];
__device__ float g_kvn[NTOK * EMB];
__device__ float g_q  [NTOK * EMB];
__device__ float g_k  [NTOK * EMB];
__device__ float g_v  [NTOK * EMB];
__device__ float g_ctx[NTOK * EMB];
__device__ unsigned char g_kvm[BATCH * NK];
__device__ unsigned char g_spm[SPM_N];
__device__ int g_is_byte[2];

// ---------------- mask dtype sniff + canonicalization ------------------------
// bool tensors may arrive as 1-byte bool or as int32 {0,1}. If int32, every
// byte at offset %4 != 0 within the first 8192 bytes is zero; if 1-byte bool,
// ~half of those bytes are 1 (deterministic given fixed inputs).
__global__ void detect_mask_kernel(const unsigned char* kvm_raw,
                                   const unsigned char* spm_raw) {
    __shared__ int found[2];
    if (threadIdx.x == 0) { found[0] = 0; found[1] = 0; }
    __syncthreads();
    for (int i = threadIdx.x; i < 8192; i += blockDim.x) {
        if ((i & 3) != 0) {
            if (kvm_raw[i]) atomicOr(&found[0], 1);
            if (spm_raw[i]) atomicOr(&found[1], 1);
        }
    }
    __syncthreads();
    if (threadIdx.x == 0) { g_is_byte[0] = found[0]; g_is_byte[1] = found[1]; }
}

__global__ void expand_kv_kernel(const void* raw) {
    int i = blockIdx.x * blockDim.x + threadIdx.x;
    if (i < BATCH * NK) {
        unsigned char v = g_is_byte[0] ? (((const unsigned char*)raw)[i] != 0)
                                       : (((const int*)raw)[i] != 0);
        g_kvm[i] = v;
    }
}

__global__ void expand_sp_kernel(const void* raw) {
    int i = blockIdx.x * blockDim.x + threadIdx.x;
    if (i < SPM_N) {
        unsigned char v = g_is_byte[1] ? (((const unsigned char*)raw)[i] != 0)
                                       : (((const int*)raw)[i] != 0);
        g_spm[i] = v;
    }
}

// ---------------- LayerNorm: one block (128 threads) per 512-elem row --------
__global__ void lnorm_kernel(const float* __restrict__ x,
                             const float* __restrict__ g,
                             const float* __restrict__ b,
                             float* __restrict__ y) {
    __shared__ float red[8];
    int row = blockIdx.x;
    int t   = threadIdx.x;                       // 0..127
    float4 v = ((const float4*)(x + (size_t)row * EMB))[t];
    float s  = v.x + v.y + v.z + v.w;
    float s2 = v.x*v.x + v.y*v.y + v.z*v.z + v.w*v.w;
    #pragma unroll
    for (int o = 16; o > 0; o >>= 1) {
        s  += __shfl_xor_sync(0xffffffffu, s,  o);
        s2 += __shfl_xor_sync(0xffffffffu, s2, o);
    }
    if ((t & 31) == 0) { red[t >> 5] = s; red[4 + (t >> 5)] = s2; }
    __syncthreads();
    float tot  = red[0] + red[1] + red[2] + red[3];
    float tot2 = red[4] + red[5] + red[6] + red[7];
    float mu  = tot  * (1.0f / EMB);
    float var = tot2 * (1.0f / EMB) - mu * mu;
    float inv = rsqrtf(var + 1e-5f);
    float4 gg = ((const float4*)g)[t];
    float4 bb = ((const float4*)b)[t];
    float4 o;
    o.x = (v.x - mu) * inv * gg.x + bb.x;
    o.y = (v.y - mu) * inv * gg.y + bb.y;
    o.z = (v.z - mu) * inv * gg.z + bb.z;
    o.w = (v.w - mu) * inv * gg.w + bb.w;
    ((float4*)(y + (size_t)row * EMB))[t] = o;
}

// ---------------- Tiled fp32 GEMM: Y[M,512] = X[M,512] @ W[512,512] + bias ---
// BM=128, BN=64, BK=16, 256 threads, 8x4 per-thread tile.
__global__ void gemm_bias_kernel(const float* __restrict__ X,
                                 const float* __restrict__ W,
                                 const float* __restrict__ bias,
                                 float* __restrict__ Y) {
    const int BM = 128, BN = 64, BK = 16;
    __shared__ float As[BK][BM];   // transposed A tile
    __shared__ float Bs[BK][BN];
    int bm  = blockIdx.y * BM;
    int bn  = blockIdx.x * BN;
    int tid = threadIdx.x;
    int tr  = tid >> 4;            // 0..15 -> rows tr*8..+7
    int tc  = tid & 15;            // 0..15 -> cols tc*4..+3

    float acc[8][4];
    #pragma unroll
    for (int i = 0; i < 8; i++)
        #pragma unroll
        for (int j = 0; j < 4; j++) acc[i][j] = 0.0f;

    for (int k0 = 0; k0 < EMB; k0 += BK) {
        #pragma unroll
        for (int i = 0; i < 2; i++) {
            int s   = tid * 2 + i;            // 0..511 float4 slots (128x16)
            int row = s >> 2;
            int c4  = s & 3;
            float4 a = *(const float4*)(X + (size_t)(bm + row) * EMB + k0 + c4 * 4);
            As[c4*4+0][row] = a.x;
            As[c4*4+1][row] = a.y;
            As[c4*4+2][row] = a.z;
            As[c4*4+3][row] = a.w;
        }
        {
            int row = tid >> 4;               // 0..15
            int c4  = tid & 15;               // 0..15
            *(float4*)&Bs[row][c4*4] =
                *(const float4*)(W + (size_t)(k0 + row) * EMB + bn + c4 * 4);
        }
        __syncthreads();
        #pragma unroll
        for (int kk = 0; kk < BK; kk++) {
            float a[8], bf[4];
            #pragma unroll
            for (int i = 0; i < 8; i++) a[i] = As[kk][tr * 8 + i];
            #pragma unroll
            for (int j = 0; j < 4; j++) bf[j] = Bs[kk][tc * 4 + j];
            #pragma unroll
            for (int i = 0; i < 8; i++)
                #pragma unroll
                for (int j = 0; j < 4; j++) acc[i][j] += a[i] * bf[j];
        }
        __syncthreads();
    }

    float4 bb = *(const float4*)(bias + bn + tc * 4);
    #pragma unroll
    for (int i = 0; i < 8; i++) {
        float4 o;
        o.x = acc[i][0] + bb.x;
        o.y = acc[i][1] + bb.y;
        o.z = acc[i][2] + bb.z;
        o.w = acc[i][3] + bb.w;
        *(float4*)(Y + (size_t)(bm + tr * 8 + i) * EMB + bn + tc * 4) = o;
    }
}

// ---------------- Fused flash attention (fp32, streaming online softmax) -----
// Block: (b, h, 64-query tile), 256 threads. Thread t: row r=t/4, sub=t&3.
// Per tile of 64 keys: scores for keys [sub*16, sub*16+16), online softmax
// across 4 lanes (shfl), P stored per-warp in smem, PV over d-slice sub*16..+15.
#define PPAD 68   // padded row stride (floats), 16B-aligned, bank-friendly
__global__ void attn_kernel(const float* __restrict__ Qp,
                            const float* __restrict__ Kp,
                            const float* __restrict__ Vp,
                            float* __restrict__ ctx) {
    extern __shared__ float sm[];
    float* Qs  = sm;                 // [64][PPAD]  Q[r][d]
    float* Kst = sm + 64 * PPAD;     // [64][PPAD]  K^T: [d][key]
    float* Vs  = sm + 2 * 64 * PPAD; // [64][PPAD]  V[key][d]
    float* Ps  = sm + 3 * 64 * PPAD; // [64][PPAD]  P[r][key]

    int qt  = blockIdx.x;            // 0..31
    int h   = blockIdx.y;            // 0..7
    int b   = blockIdx.z;            // 0..3
    int tid = threadIdx.x;
    int r   = tid >> 2;              // 0..63
    int sub = tid & 3;               // 0..3
    int q_global = qt * 64 + r;

    // load Q tile [64 rows x 64 dims]
    #pragma unroll
    for (int i = 0; i < 4; i++) {
        int s   = tid + i * 256;     // 1024 float4 slots
        int row = s >> 4;
        int d4  = s & 15;
        float4 v = *(const float4*)(Qp + (size_t)(b * NQ + qt * 64 + row) * EMB + h * HD + d4 * 4);
        *(float4*)&Qs[row * PPAD + d4 * 4] = v;
    }

    float m = -1e30f, l = 0.0f;
    float acc[16];
    #pragma unroll
    for (int i = 0; i < 16; i++) acc[i] = 0.0f;

    const unsigned char* kvm = g_kvm + b * NK;
    const unsigned char* spm = g_spm + ((size_t)b * NQ + q_global) * NK;
    const float scale = 0.125f;      // 64^-0.5
    const int kbase = sub * 16;
    const int dbase = sub * 16;

    for (int k0 = 0; k0 < NK; k0 += 64) {
        __syncthreads();             // prev tile reads done before overwrite
        // load K (transposed) and V tiles
        #pragma unroll
        for (int i = 0; i < 4; i++) {
            int s   = tid + i * 256;
            int key = s >> 4;
            int d4  = s & 15;
            size_t base = (size_t)(b * NK + k0 + key) * EMB + h * HD + d4 * 4;
            float4 kv4 = *(const float4*)(Kp + base);
            Kst[(d4*4+0) * PPAD + key] = kv4.x;
            Kst[(d4*4+1) * PPAD + key] = kv4.y;
            Kst[(d4*4+2) * PPAD + key] = kv4.z;
            Kst[(d4*4+3) * PPAD + key] = kv4.w;
            float4 vv = *(const float4*)(Vp + base);
            *(float4*)&Vs[key * PPAD + d4 * 4] = vv;
        }
        __syncthreads();

        // scores: this thread's 16 keys for its row
        float s16[16];
        #pragma unroll
        for (int j = 0; j < 16; j++) s16[j] = 0.0f;
        #pragma unroll 8
        for (int d = 0; d < HD; d++) {
            float qd = Qs[r * PPAD + d];
            const float* krow = &Kst[d * PPAD + kbase];
            #pragma unroll
            for (int j = 0; j < 16; j++) s16[j] += qd * krow[j];
        }

        // mask + scale + tile max
        float tmax = -1e30f;
        #pragma unroll
        for (int j = 0; j < 16; j++) {
            int k = k0 + kbase + j;
            bool valid = (kvm[k] != 0) && (spm[k] != 0);
            s16[j] = valid ? s16[j] * scale : -1e30f;
            tmax = fmaxf(tmax, s16[j]);
        }
        tmax = fmaxf(tmax, __shfl_xor_sync(0xffffffffu, tmax, 1));
        tmax = fmaxf(tmax, __shfl_xor_sync(0xffffffffu, tmax, 2));

        float mnew = fmaxf(m, tmax);
        float corr = __expf(m - mnew);   // both -1e30 -> exp(0)=1, acc is 0 anyway
        float psum = 0.0f;
        #pragma unroll
        for (int j = 0; j < 16; j++) {
            float p = (s16[j] > -1e29f) ? __expf(s16[j] - mnew) : 0.0f;
            s16[j] = p;
            psum += p;
        }
        psum += __shfl_xor_sync(0xffffffffu, psum, 1);
        psum += __shfl_xor_sync(0xffffffffu, psum, 2);
        l = l * corr + psum;
        m = mnew;
        #pragma unroll
        for (int i = 0; i < 16; i++) acc[i] *= corr;

        // stage P (only same-warp lanes read it: rows 0..7 of each warp)
        #pragma unroll
        for (int j = 0; j < 16; j += 4)
            *(float4*)&Ps[r * PPAD + kbase + j] =
                make_float4(s16[j], s16[j+1], s16[j+2], s16[j+3]);
        __syncwarp();

        // PV: acc[dbase..dbase+15] += sum_k P[r][k] * V[k][d]
        #pragma unroll 8
        for (int k = 0; k < 64; k++) {
            float p = Ps[r * PPAD + k];
            const float* vrow = &Vs[k * PPAD + dbase];
            #pragma unroll
            for (int j = 0; j < 16; j++) acc[j] += p * vrow[j];
        }
        __syncwarp();
    }

    float invl = (l > 0.0f) ? (1.0f / l) : 0.0f;
    float* op = ctx + (size_t)(b * NQ + q_global) * EMB + h * HD + dbase;
    #pragma unroll
    for (int j = 0; j < 16; j += 4)
        *(float4*)(op + j) = make_float4(acc[j] * invl, acc[j+1] * invl,
                                         acc[j+2] * invl, acc[j+3] * invl);
}

// ---------------- launch ------------------------------------------------------
extern "C" void kernel_launch(void* const* d_in, const int* in_sizes, int n_in,
                              void* d_out, int out_size) {
    const float* query     = (const float*)d_in[0];
    const float* key_value = (const float*)d_in[1];
    const void*  kvm_raw   = d_in[2];
    const void*  spm_raw   = d_in[3];
    const float* ln_q_g    = (const float*)d_in[4];
    const float* ln_q_b    = (const float*)d_in[5];
    const float* ln_kv_g   = (const float*)d_in[6];
    const float* ln_kv_b   = (const float*)d_in[7];
    const float* Wq = (const float*)d_in[8];
    const float* bq = (const float*)d_in[9];
    const float* Wk = (const float*)d_in[10];
    const float* bk = (const float*)d_in[11];
    const float* Wv = (const float*)d_in[12];
    const float* bv = (const float*)d_in[13];
    const float* Wo = (const float*)d_in[14];
    const float* bo = (const float*)d_in[15];
    float* out = (float*)d_out;

    void *p_qn, *p_kvn, *p_q, *p_k, *p_v, *p_ctx;
    cudaGetSymbolAddress(&p_qn,  g_qn);
    cudaGetSymbolAddress(&p_kvn, g_kvn);
    cudaGetSymbolAddress(&p_q,   g_q);
    cudaGetSymbolAddress(&p_k,   g_k);
    cudaGetSymbolAddress(&p_v,   g_v);
    cudaGetSymbolAddress(&p_ctx, g_ctx);

    // masks
    detect_mask_kernel<<<1, 256>>>((const unsigned char*)kvm_raw,
                                   (const unsigned char*)spm_raw);
    expand_kv_kernel<<<(BATCH * NK + 255) / 256, 256>>>(kvm_raw);
    expand_sp_kernel<<<SPM_N / 256, 256>>>(spm_raw);

    // layernorms
    lnorm_kernel<<<NTOK, 128>>>(query,     ln_q_g,  ln_q_b,  (float*)p_qn);
    lnorm_kernel<<<NTOK, 128>>>(key_value, ln_kv_g, ln_kv_b, (float*)p_kvn);

    // Q/K/V projections
    dim3 ggrid(EMB / 64, NTOK / 128);
    gemm_bias_kernel<<<ggrid, 256>>>((const float*)p_qn,  Wq, bq, (float*)p_q);
    gemm_bias_kernel<<<ggrid, 256>>>((const float*)p_kvn, Wk, bk, (float*)p_k);
    gemm_bias_kernel<<<ggrid, 256>>>((const float*)p_kvn, Wv, bv, (float*)p_v);

    // fused attention
    int smem_bytes = 4 * 64 * PPAD * (int)sizeof(float);   // 69632
    cudaFuncSetAttribute(attn_kernel,
                         cudaFuncAttributeMaxDynamicSharedMemorySize, smem_bytes);
    dim3 agrid(NQ / 64, NH, BATCH);
    attn_kernel<<<agrid, 256, smem_bytes>>>((const float*)p_q, (const float*)p_k,
                                            (const float*)p_v, (float*)p_ctx);

    // output projection
    gemm_bias_kernel<<<ggrid, 256>>>((const float*)p_ctx, Wo, bo, out);
}